// round 13
// baseline (speedup 1.0000x reference)
#include <cuda_runtime.h>
#include <cuda_fp16.h>
#include <cstdint>

#define NN 50000
#define NE 800000
#define DD 256
#define SCAN_BLK 512
#define SCAN_NB  ((NN + SCAN_BLK - 1) / SCAN_BLK)   // 98
#define ASW 12    // As row stride in words (16 halves + pad) - conflict-free A frags
#define BSW 136   // Bs2 row stride in words (128 half2 + pad) - conflict-free B frags

// Static scratch (no allocations allowed): ~88 MB.
__device__ float g_x[NN * DD];                      // fp32 activations
__device__ __align__(16) __half g_hh[NN * DD];      // fp16 post-GEMM h
__device__ float g_dinv[NN];
__device__ int   g_src[NE];
__device__ int   g_dst[NE];
__device__ int   g_esrc[NE];        // CSR: src ids grouped by dst
__device__ int   g_cnt[NN];         // in-degree (edges only)
__device__ int   g_rowstart[NN + 1];
__device__ int   g_fill[NN];
__device__ int   g_bsum[SCAN_NB];
__device__ int   g_boff[SCAN_NB];
__device__ int   g_odd_nonzero;     // dtype sniffer flag
__device__ int   g_scan_done;       // fused-scan arrival counter
__device__ int   g_scan_ready;      // fused-scan release flag

// bitcast __half2 -> uint32_t (no intrinsic exists for this direction)
__device__ __forceinline__ uint32_t h2u(__half2 h) {
    union { __half2 h; uint32_t u; } c;
    c.h = h;
    return c.u;
}

// ---------------------------------------------------------------------------
// Setup kernel 1: zero cnt + scan flags; block 0 also sniffs edge dtype.
// int64 edge data viewed as int32 words has all odd words == 0 (values < 50000).
// Block 0 reduces OR over odd words [0, 8192) and plain-stores the flag
// (no atomics -> no pre-zero ordering hazard).
// ---------------------------------------------------------------------------
__global__ void init_kernel(const int* __restrict__ ei32) {
    int i = blockIdx.x * blockDim.x + threadIdx.x;
    if (i < NN) g_cnt[i] = 0;
    if (blockIdx.x == 0) {
        __shared__ int sor[256];
        int t = threadIdx.x;
        int v = 0;
#pragma unroll
        for (int j = 0; j < 16; j++) {          // 256 threads * 16 odd words = [0,8192)
            int w = (t * 16 + j) * 2 + 1;
            v |= ei32[w];
        }
        sor[t] = v;
        __syncthreads();
        for (int off = 128; off > 0; off >>= 1) {
            if (t < off) sor[t] |= sor[t + off];
            __syncthreads();
        }
        if (t == 0) {
            g_odd_nonzero = (sor[0] != 0);
            g_scan_done  = 0;
            g_scan_ready = 0;
        }
    }
}

__global__ void decode_hist_kernel(const int* __restrict__ ei32) {
    int e = blockIdx.x * blockDim.x + threadIdx.x;
    if (e >= NE) return;
    int s, d;
    if (g_odd_nonzero) {            // genuinely int32: [src[NE] | dst[NE]]
        s = ei32[e];
        d = ei32[NE + e];
    } else {                        // int64: low words at even offsets
        s = ei32[2 * e];
        d = ei32[2 * (NE + e)];
    }
    g_src[e] = s;
    g_dst[e] = d;
    atomicAdd(&g_cnt[d], 1);
}

// ---------------------------------------------------------------------------
// Setup kernel 3: fused 3-pass scan (single wave: 98 blocks, all resident).
// Each block scans its 512 counts; last-arriving block scans the 98 block
// sums and releases everyone; then all blocks write rowstart/dinv/fill.
// ---------------------------------------------------------------------------
__global__ void __launch_bounds__(SCAN_BLK) scan_fused_kernel() {
    __shared__ int s[SCAN_BLK];
    const int t = threadIdx.x;
    const int b = blockIdx.x;
    const int i = b * SCAN_BLK + t;
    const int v = (i < NN) ? g_cnt[i] : 0;
    s[t] = v;
    __syncthreads();
    for (int off = 1; off < SCAN_BLK; off <<= 1) {
        int x = s[t];
        int add = (t >= off) ? s[t - off] : 0;
        __syncthreads();
        s[t] = x + add;
        __syncthreads();
    }
    const int incl = s[t];               // inclusive local prefix
    const int bsum = s[SCAN_BLK - 1];

    if (t == 0) {
        g_bsum[b] = bsum;
        __threadfence();
        if (atomicAdd(&g_scan_done, 1) == SCAN_NB - 1) {
            int run = 0;
            for (int j = 0; j < SCAN_NB; j++) {   // 98 elems, pipelined loads
                g_boff[j] = run;
                run += g_bsum[j];
            }
            __threadfence();
            atomicExch(&g_scan_ready, 1);
        }
        while (atomicAdd(&g_scan_ready, 0) == 0) {}
    }
    __syncthreads();

    const int off = g_boff[b];
    if (i < NN) {
        g_rowstart[i] = off + incl - v;
        g_fill[i] = 0;
        g_dinv[i] = rsqrtf((float)v + 1.0f);   // +1 self loop
    }
    if (i == 0) g_rowstart[NN] = NE;
}

__global__ void fill_kernel() {
    int e = blockIdx.x * blockDim.x + threadIdx.x;
    if (e >= NE) return;
    int d = g_dst[e];
    int pos = g_rowstart[d] + atomicAdd(&g_fill[d], 1);
    g_esrc[pos] = g_src[e];
}

// ---------------------------------------------------------------------------
// FP16 tensor-core GEMM: C[M,256] = A[M,256] @ B[256,256] (+bias, +relu)
// 128x128 tile, 256 threads (8 warps, 2M x 4N), warp tile 64x32,
// mma.sync.m16n8k16.f16 (fp32 accum), BK=16, register-prefetch pipeline.
// a_sel: 0 -> A = Ain (external), 1 -> A = g_x
// c_sel: 0 -> C = g_x (fp32),     1 -> C = g_hh (fp16)
// ---------------------------------------------------------------------------
__global__ void __launch_bounds__(256)
gemm_kernel(const float* __restrict__ Ain, const float* __restrict__ B,
            const float* __restrict__ bias, int a_sel, int c_sel, int relu)
{
    const float* A = (a_sel == 0) ? Ain : g_x;

    __shared__ uint32_t As[128 * ASW];   // [m][k] halves (packed half2 words)
    __shared__ uint32_t Bs2[8 * BSW];    // [kpair][n] half2

    const int tid  = threadIdx.x;
    const int lane = tid & 31;
    const int w    = tid >> 5;
    const int mw   = (w & 1) << 6;      // warp M offset: 0 / 64
    const int nw   = (w >> 1) << 5;     // warp N offset: 0/32/64/96
    const int gid  = lane >> 2;         // 0..7
    const int tg   = lane & 3;          // 0..3
    const int row0 = blockIdx.x * 128;
    const int col0 = blockIdx.y * 128;

    const int ar0 = tid >> 2,          ak0 = (tid & 3) * 4;
    const int ar1 = (tid + 256) >> 2,  ak1 = ak0;
    const int bp  = tid >> 5;
    const int bn4 = (tid & 31) * 4;

    float acc[4][4][4];
#pragma unroll
    for (int mt = 0; mt < 4; mt++)
#pragma unroll
        for (int nt = 0; nt < 4; nt++)
#pragma unroll
            for (int q = 0; q < 4; q++) acc[mt][nt][q] = 0.0f;

    float4 av0, av1, bv0, bv1;

    // prefetch chunk 0
    {
        int r0 = row0 + ar0, r1 = row0 + ar1;
        av0 = (r0 < NN) ? *(const float4*)&A[(size_t)r0 * DD + ak0] : make_float4(0,0,0,0);
        av1 = (r1 < NN) ? *(const float4*)&A[(size_t)r1 * DD + ak1] : make_float4(0,0,0,0);
        bv0 = *(const float4*)&B[(size_t)(2 * bp)     * DD + col0 + bn4];
        bv1 = *(const float4*)&B[(size_t)(2 * bp + 1) * DD + col0 + bn4];
    }

    for (int c = 0; c < 16; c++) {
        __syncthreads();
        // store prefetched chunk to smem (cvt to fp16)
        {
            uint2 aw;
            aw.x = h2u(__floats2half2_rn(av0.x, av0.y));
            aw.y = h2u(__floats2half2_rn(av0.z, av0.w));
            *(uint2*)&As[ar0 * ASW + (ak0 >> 1)] = aw;
            aw.x = h2u(__floats2half2_rn(av1.x, av1.y));
            aw.y = h2u(__floats2half2_rn(av1.z, av1.w));
            *(uint2*)&As[ar1 * ASW + (ak1 >> 1)] = aw;
            uint4 bw;
            bw.x = h2u(__floats2half2_rn(bv0.x, bv1.x));
            bw.y = h2u(__floats2half2_rn(bv0.y, bv1.y));
            bw.z = h2u(__floats2half2_rn(bv0.z, bv1.z));
            bw.w = h2u(__floats2half2_rn(bv0.w, bv1.w));
            *(uint4*)&Bs2[bp * BSW + bn4] = bw;
        }
        __syncthreads();
        // prefetch next chunk (latency hidden behind MMAs below)
        if (c < 15) {
            int k0 = (c + 1) * 16;
            int r0 = row0 + ar0, r1 = row0 + ar1;
            av0 = (r0 < NN) ? *(const float4*)&A[(size_t)r0 * DD + k0 + ak0] : make_float4(0,0,0,0);
            av1 = (r1 < NN) ? *(const float4*)&A[(size_t)r1 * DD + k0 + ak1] : make_float4(0,0,0,0);
            bv0 = *(const float4*)&B[(size_t)(k0 + 2 * bp)     * DD + col0 + bn4];
            bv1 = *(const float4*)&B[(size_t)(k0 + 2 * bp + 1) * DD + col0 + bn4];
        }
        // compute chunk c: one k16 step, 4x4 mma m16n8k16
        {
            uint32_t bf[4][2];
#pragma unroll
            for (int nt = 0; nt < 4; nt++) {
                int n = nw + nt * 8 + gid;
                bf[nt][0] = Bs2[tg * BSW + n];
                bf[nt][1] = Bs2[(tg + 4) * BSW + n];
            }
#pragma unroll
            for (int mt = 0; mt < 4; mt++) {
                int m = mw + mt * 16 + gid;
                uint32_t a0 = As[m * ASW + tg];
                uint32_t a1 = As[(m + 8) * ASW + tg];
                uint32_t a2 = As[m * ASW + tg + 4];
                uint32_t a3 = As[(m + 8) * ASW + tg + 4];
#pragma unroll
                for (int nt = 0; nt < 4; nt++) {
                    asm("mma.sync.aligned.m16n8k16.row.col.f32.f16.f16.f32 "
                        "{%0,%1,%2,%3}, {%4,%5,%6,%7}, {%8,%9}, {%0,%1,%2,%3};"
                        : "+f"(acc[mt][nt][0]), "+f"(acc[mt][nt][1]),
                          "+f"(acc[mt][nt][2]), "+f"(acc[mt][nt][3])
                        : "r"(a0), "r"(a1), "r"(a2), "r"(a3),
                          "r"(bf[nt][0]), "r"(bf[nt][1]));
                }
            }
        }
    }

    // epilogue
    float2 bb[4];
    if (bias) {
#pragma unroll
        for (int nt = 0; nt < 4; nt++) {
            int cc = col0 + nw + nt * 8 + 2 * tg;
            bb[nt].x = bias[cc];
            bb[nt].y = bias[cc + 1];
        }
    }
#pragma unroll
    for (int mt = 0; mt < 4; mt++) {
        int r = row0 + mw + mt * 16 + gid;
#pragma unroll
        for (int nt = 0; nt < 4; nt++) {
            int cc = col0 + nw + nt * 8 + 2 * tg;
            float2 v0 = make_float2(acc[mt][nt][0], acc[mt][nt][1]);
            float2 v1 = make_float2(acc[mt][nt][2], acc[mt][nt][3]);
            if (bias) {
                v0.x += bb[nt].x; v0.y += bb[nt].y;
                v1.x += bb[nt].x; v1.y += bb[nt].y;
            }
            if (relu) {
                v0.x = fmaxf(v0.x, 0.f); v0.y = fmaxf(v0.y, 0.f);
                v1.x = fmaxf(v1.x, 0.f); v1.y = fmaxf(v1.y, 0.f);
            }
            if (c_sel == 0) {
                if (r < NN)     *(float2*)&g_x[(size_t)r * DD + cc]       = v0;
                if (r + 8 < NN) *(float2*)&g_x[(size_t)(r + 8) * DD + cc] = v1;
            } else {
                if (r < NN)     *(__half2*)&g_hh[(size_t)r * DD + cc]       = __floats2half2_rn(v0.x, v0.y);
                if (r + 8 < NN) *(__half2*)&g_hh[(size_t)(r + 8) * DD + cc] = __floats2half2_rn(v1.x, v1.y);
            }
        }
    }
}

// ---------------------------------------------------------------------------
// Fused CSR aggregation (fp16 h): one warp per dst node, 4-edge unroll.
//   o[d] = relu( bias + dinv[d]^2 * h[d] + sum_{s in N(d)} dinv[s]dinv[d] h[s] )
// Lane holds 8 contiguous cols [lane*8, lane*8+8): ONE uint4 load per edge-row.
// ---------------------------------------------------------------------------
__device__ __forceinline__ void acc8(float* a, uint4 raw, float n) {
    const __half2* h2 = (const __half2*)&raw;
#pragma unroll
    for (int j = 0; j < 4; j++) {
        float2 f = __half22float2(h2[j]);
        a[2 * j + 0] += n * f.x;
        a[2 * j + 1] += n * f.y;
    }
}

__global__ void __launch_bounds__(256)
aggregate_kernel(const float* __restrict__ bias, float* __restrict__ Oin, int o_sel)
{
    float* o = (o_sel == 0) ? g_x : Oin;
    int warp = (blockIdx.x * blockDim.x + threadIdx.x) >> 5;
    int lane = threadIdx.x & 31;
    if (warp >= NN) return;
    const int d = warp;
    const float dv = g_dinv[d];

    float a[8];
    // self-loop init
    {
        uint4 raw = *((const uint4*)(g_hh + (size_t)d * DD) + lane);
        const __half2* h2 = (const __half2*)&raw;
        const float s2 = dv * dv;
#pragma unroll
        for (int j = 0; j < 4; j++) {
            float2 f = __half22float2(h2[j]);
            a[2 * j + 0] = s2 * f.x;
            a[2 * j + 1] = s2 * f.y;
        }
    }

    const int start = g_rowstart[d];
    const int end   = g_rowstart[d + 1];
    int i = start;
    for (; i + 4 <= end; i += 4) {
        int   s0 = g_esrc[i],     s1 = g_esrc[i + 1];
        int   s2 = g_esrc[i + 2], s3 = g_esrc[i + 3];
        float n0 = dv * g_dinv[s0], n1 = dv * g_dinv[s1];
        float n2 = dv * g_dinv[s2], n3 = dv * g_dinv[s3];
        uint4 r0 = *((const uint4*)(g_hh + (size_t)s0 * DD) + lane);
        uint4 r1 = *((const uint4*)(g_hh + (size_t)s1 * DD) + lane);
        uint4 r2 = *((const uint4*)(g_hh + (size_t)s2 * DD) + lane);
        uint4 r3 = *((const uint4*)(g_hh + (size_t)s3 * DD) + lane);
        acc8(a, r0, n0);
        acc8(a, r1, n1);
        acc8(a, r2, n2);
        acc8(a, r3, n3);
    }
    for (; i < end; i++) {
        int s0 = g_esrc[i];
        float n0 = dv * g_dinv[s0];
        uint4 r0 = *((const uint4*)(g_hh + (size_t)s0 * DD) + lane);
        acc8(a, r0, n0);
    }

    // bias + relu + store (cols lane*8 .. lane*8+7)
    const int cbase = lane * 8;
    float4 b0 = *(const float4*)&bias[cbase];
    float4 b1 = *(const float4*)&bias[cbase + 4];
    float4 v0, v1;
    v0.x = fmaxf(a[0] + b0.x, 0.f); v0.y = fmaxf(a[1] + b0.y, 0.f);
    v0.z = fmaxf(a[2] + b0.z, 0.f); v0.w = fmaxf(a[3] + b0.w, 0.f);
    v1.x = fmaxf(a[4] + b1.x, 0.f); v1.y = fmaxf(a[5] + b1.y, 0.f);
    v1.z = fmaxf(a[6] + b1.z, 0.f); v1.w = fmaxf(a[7] + b1.w, 0.f);
    float* orow = o + (size_t)d * DD + cbase;
    *(float4*)&orow[0] = v0;
    *(float4*)&orow[4] = v1;
}

// ---------------------------------------------------------------------------
// Launch — kernels only; no runtime API calls (graph-capture safe).
// ---------------------------------------------------------------------------
extern "C" void kernel_launch(void* const* d_in, const int* in_sizes, int n_in,
                              void* d_out, int out_size)
{
    const float* input  = (const float*)d_in[0];
    const int*   ei32   = (const int*)d_in[1];     // int32 view; dtype sniffed on device
    const float* weight = (const float*)d_in[2];
    const float* bias   = (const float*)d_in[3];
    const float* conv_w = (const float*)d_in[4];
    const float* conv_b = (const float*)d_in[5];
    float*       out    = (float*)d_out;

    // CSR build (4 kernels)
    init_kernel<<<(NN + 255) / 256, 256>>>(ei32);
    decode_hist_kernel<<<(NE + 255) / 256, 256>>>(ei32);
    scan_fused_kernel<<<SCAN_NB, SCAN_BLK>>>();
    fill_kernel<<<(NE + 255) / 256, 256>>>();

    dim3 ggrid((NN + 127) / 128, DD / 128);

    // x = relu(input @ W + b)   (A = input, C = g_x fp32)
    gemm_kernel<<<ggrid, 256>>>(input, weight, bias, /*a_sel=*/0, /*c_sel=*/0, /*relu=*/1);

    const int agg_blocks = (NN * 32 + 255) / 256;   // warp per node
    for (int l = 0; l < 2; l++) {
        // h = x @ conv_w[l]   (A = g_x, C = g_hh fp16)
        gemm_kernel<<<ggrid, 256>>>(nullptr, conv_w + (size_t)l * DD * DD,
                                    nullptr, /*a_sel=*/1, /*c_sel=*/1, /*relu=*/0);
        // fused: self-loop + neighbor gather + bias + relu
        aggregate_kernel<<<agg_blocks, 256>>>(conv_b + l * DD,
                                              out, /*o_sel=*/(l == 0) ? 0 : 1);
    }
}

// round 14
// speedup vs baseline: 1.0005x; 1.0005x over previous
#include <cuda_runtime.h>
#include <cuda_fp16.h>
#include <cstdint>

#define NN 50000
#define NE 800000
#define DD 256
#define EB 4                     // edges per thread in hist/fill (atomic MLP)
#define ESTRIDE (NE / EB)        // 200000
#define SCAN_BLK 512
#define SCAN_NB  ((NN + SCAN_BLK - 1) / SCAN_BLK)   // 98
#define ASW 12    // As row stride in words (16 halves + pad) - conflict-free A frags
#define BSW 136   // Bs2 row stride in words (128 half2 + pad) - conflict-free B frags

// Static scratch (no allocations allowed): ~88 MB.
__device__ float g_x[NN * DD];                      // fp32 activations
__device__ __align__(16) __half g_hh[NN * DD];      // fp16 post-GEMM h
__device__ float g_dinv[NN];
__device__ int   g_src[NE];
__device__ int   g_dst[NE];
__device__ int   g_esrc[NE];        // CSR: src ids grouped by dst
__device__ int   g_cnt[NN];         // in-degree (edges only)
__device__ int   g_rowstart[NN + 1];
__device__ int   g_fill[NN];
__device__ int   g_bsum[SCAN_NB];
__device__ int   g_boff[SCAN_NB];
__device__ int   g_odd_nonzero;     // dtype sniffer flag

// bitcast __half2 -> uint32_t (no intrinsic exists for this direction)
__device__ __forceinline__ uint32_t h2u(__half2 h) {
    union { __half2 h; uint32_t u; } c;
    c.h = h;
    return c.u;
}

// ---------------------------------------------------------------------------
// Setup 1: zero cnt; block 0 sniffs edge dtype (int64 viewed as int32 words
// has all odd words == 0 since values < 50000). Plain store, no atomics.
// ---------------------------------------------------------------------------
__global__ void init_kernel(const int* __restrict__ ei32) {
    int i = blockIdx.x * blockDim.x + threadIdx.x;
    if (i < NN) g_cnt[i] = 0;
    if (blockIdx.x == 0) {
        __shared__ int sor[256];
        int t = threadIdx.x;
        int v = 0;
#pragma unroll
        for (int j = 0; j < 16; j++) {          // 256 threads * 16 odd words = [0,8192)
            int w = (t * 16 + j) * 2 + 1;
            v |= ei32[w];
        }
        sor[t] = v;
        __syncthreads();
        for (int off = 128; off > 0; off >>= 1) {
            if (t < off) sor[t] |= sor[t + off];
            __syncthreads();
        }
        if (t == 0) g_odd_nonzero = (sor[0] != 0);
    }
}

// ---------------------------------------------------------------------------
// Setup 2: decode + histogram, EB edges per thread (grid-stride batches keep
// coalescing; EB independent atomics in flight hide ATOMG latency).
// ---------------------------------------------------------------------------
__global__ void decode_hist_kernel(const int* __restrict__ ei32) {
    int t = blockIdx.x * blockDim.x + threadIdx.x;
    if (t >= ESTRIDE) return;
    const int i32 = g_odd_nonzero;
    int s[EB], d[EB];
#pragma unroll
    for (int j = 0; j < EB; j++) {
        int e = t + j * ESTRIDE;
        if (i32) {                  // int32: [src[NE] | dst[NE]]
            s[j] = ei32[e];
            d[j] = ei32[NE + e];
        } else {                    // int64: low words at even offsets
            s[j] = ei32[2 * e];
            d[j] = ei32[2 * (NE + e)];
        }
    }
#pragma unroll
    for (int j = 0; j < EB; j++) {
        int e = t + j * ESTRIDE;
        g_src[e] = s[j];
        g_dst[e] = d[j];
    }
#pragma unroll
    for (int j = 0; j < EB; j++) atomicAdd(&g_cnt[d[j]], 1);
}

// Pass 1: per-block sums of g_cnt
__global__ void __launch_bounds__(SCAN_BLK) partial_sum_kernel() {
    __shared__ int s[SCAN_BLK];
    int t = threadIdx.x;
    int i = blockIdx.x * SCAN_BLK + t;
    s[t] = (i < NN) ? g_cnt[i] : 0;
    __syncthreads();
    for (int off = SCAN_BLK / 2; off > 0; off >>= 1) {
        if (t < off) s[t] += s[t + off];
        __syncthreads();
    }
    if (t == 0) g_bsum[blockIdx.x] = s[0];
}

// Pass 2: exclusive scan of 98 block sums (1 small block)
__global__ void __launch_bounds__(128) scan_partials_kernel() {
    __shared__ int s[128];
    int t = threadIdx.x;
    int v = (t < SCAN_NB) ? g_bsum[t] : 0;
    s[t] = v;
    __syncthreads();
    for (int off = 1; off < 128; off <<= 1) {
        int x = s[t];
        int add = (t >= off) ? s[t - off] : 0;
        __syncthreads();
        s[t] = x + add;
        __syncthreads();
    }
    if (t < SCAN_NB) g_boff[t] = s[t] - v;   // exclusive
}

// Pass 3: per-block local scan + offset; writes rowstart, dinv, fill
__global__ void __launch_bounds__(SCAN_BLK) write_rows_kernel() {
    __shared__ int s[SCAN_BLK];
    int t = threadIdx.x;
    int i = blockIdx.x * SCAN_BLK + t;
    int v = (i < NN) ? g_cnt[i] : 0;
    s[t] = v;
    __syncthreads();
    for (int off = 1; off < SCAN_BLK; off <<= 1) {
        int x = s[t];
        int add = (t >= off) ? s[t - off] : 0;
        __syncthreads();
        s[t] = x + add;
        __syncthreads();
    }
    if (i < NN) {
        g_rowstart[i] = g_boff[blockIdx.x] + s[t] - v;
        g_fill[i] = 0;
        g_dinv[i] = rsqrtf((float)v + 1.0f);   // +1 self loop
    }
    if (i == 0) g_rowstart[NN] = NE;
}

// ---------------------------------------------------------------------------
// Setup 5: CSR fill, EB edges per thread (EB cursor atomics in flight).
// ---------------------------------------------------------------------------
__global__ void fill_kernel() {
    int t = blockIdx.x * blockDim.x + threadIdx.x;
    if (t >= ESTRIDE) return;
    int s[EB], d[EB], pos[EB];
#pragma unroll
    for (int j = 0; j < EB; j++) {
        int e = t + j * ESTRIDE;
        s[j] = g_src[e];
        d[j] = g_dst[e];
    }
#pragma unroll
    for (int j = 0; j < EB; j++)
        pos[j] = g_rowstart[d[j]] + atomicAdd(&g_fill[d[j]], 1);
#pragma unroll
    for (int j = 0; j < EB; j++)
        g_esrc[pos[j]] = s[j];
}

// ---------------------------------------------------------------------------
// FP16 tensor-core GEMM: C[M,256] = A[M,256] @ B[256,256] (+bias, +relu)
// 128x128 tile, 256 threads (8 warps, 2M x 4N), warp tile 64x32,
// mma.sync.m16n8k16.f16 (fp32 accum), BK=16, register-prefetch pipeline.
// a_sel: 0 -> A = Ain (external), 1 -> A = g_x
// c_sel: 0 -> C = g_x (fp32),     1 -> C = g_hh (fp16)
// ---------------------------------------------------------------------------
__global__ void __launch_bounds__(256)
gemm_kernel(const float* __restrict__ Ain, const float* __restrict__ B,
            const float* __restrict__ bias, int a_sel, int c_sel, int relu)
{
    const float* A = (a_sel == 0) ? Ain : g_x;

    __shared__ uint32_t As[128 * ASW];   // [m][k] halves (packed half2 words)
    __shared__ uint32_t Bs2[8 * BSW];    // [kpair][n] half2

    const int tid  = threadIdx.x;
    const int lane = tid & 31;
    const int w    = tid >> 5;
    const int mw   = (w & 1) << 6;      // warp M offset: 0 / 64
    const int nw   = (w >> 1) << 5;     // warp N offset: 0/32/64/96
    const int gid  = lane >> 2;         // 0..7
    const int tg   = lane & 3;          // 0..3
    const int row0 = blockIdx.x * 128;
    const int col0 = blockIdx.y * 128;

    const int ar0 = tid >> 2,          ak0 = (tid & 3) * 4;
    const int ar1 = (tid + 256) >> 2,  ak1 = ak0;
    const int bp  = tid >> 5;
    const int bn4 = (tid & 31) * 4;

    float acc[4][4][4];
#pragma unroll
    for (int mt = 0; mt < 4; mt++)
#pragma unroll
        for (int nt = 0; nt < 4; nt++)
#pragma unroll
            for (int q = 0; q < 4; q++) acc[mt][nt][q] = 0.0f;

    float4 av0, av1, bv0, bv1;

    // prefetch chunk 0
    {
        int r0 = row0 + ar0, r1 = row0 + ar1;
        av0 = (r0 < NN) ? *(const float4*)&A[(size_t)r0 * DD + ak0] : make_float4(0,0,0,0);
        av1 = (r1 < NN) ? *(const float4*)&A[(size_t)r1 * DD + ak1] : make_float4(0,0,0,0);
        bv0 = *(const float4*)&B[(size_t)(2 * bp)     * DD + col0 + bn4];
        bv1 = *(const float4*)&B[(size_t)(2 * bp + 1) * DD + col0 + bn4];
    }

    for (int c = 0; c < 16; c++) {
        __syncthreads();
        // store prefetched chunk to smem (cvt to fp16)
        {
            uint2 aw;
            aw.x = h2u(__floats2half2_rn(av0.x, av0.y));
            aw.y = h2u(__floats2half2_rn(av0.z, av0.w));
            *(uint2*)&As[ar0 * ASW + (ak0 >> 1)] = aw;
            aw.x = h2u(__floats2half2_rn(av1.x, av1.y));
            aw.y = h2u(__floats2half2_rn(av1.z, av1.w));
            *(uint2*)&As[ar1 * ASW + (ak1 >> 1)] = aw;
            uint4 bw;
            bw.x = h2u(__floats2half2_rn(bv0.x, bv1.x));
            bw.y = h2u(__floats2half2_rn(bv0.y, bv1.y));
            bw.z = h2u(__floats2half2_rn(bv0.z, bv1.z));
            bw.w = h2u(__floats2half2_rn(bv0.w, bv1.w));
            *(uint4*)&Bs2[bp * BSW + bn4] = bw;
        }
        __syncthreads();
        // prefetch next chunk (latency hidden behind MMAs below)
        if (c < 15) {
            int k0 = (c + 1) * 16;
            int r0 = row0 + ar0, r1 = row0 + ar1;
            av0 = (r0 < NN) ? *(const float4*)&A[(size_t)r0 * DD + k0 + ak0] : make_float4(0,0,0,0);
            av1 = (r1 < NN) ? *(const float4*)&A[(size_t)r1 * DD + k0 + ak1] : make_float4(0,0,0,0);
            bv0 = *(const float4*)&B[(size_t)(k0 + 2 * bp)     * DD + col0 + bn4];
            bv1 = *(const float4*)&B[(size_t)(k0 + 2 * bp + 1) * DD + col0 + bn4];
        }
        // compute chunk c: one k16 step, 4x4 mma m16n8k16
        {
            uint32_t bf[4][2];
#pragma unroll
            for (int nt = 0; nt < 4; nt++) {
                int n = nw + nt * 8 + gid;
                bf[nt][0] = Bs2[tg * BSW + n];          // k = 2tg, 2tg+1
                bf[nt][1] = Bs2[(tg + 4) * BSW + n];    // k = 2tg+8, 2tg+9
            }
#pragma unroll
            for (int mt = 0; mt < 4; mt++) {
                int m = mw + mt * 16 + gid;
                uint32_t a0 = As[m * ASW + tg];
                uint32_t a1 = As[(m + 8) * ASW + tg];
                uint32_t a2 = As[m * ASW + tg + 4];
                uint32_t a3 = As[(m + 8) * ASW + tg + 4];
#pragma unroll
                for (int nt = 0; nt < 4; nt++) {
                    asm("mma.sync.aligned.m16n8k16.row.col.f32.f16.f16.f32 "
                        "{%0,%1,%2,%3}, {%4,%5,%6,%7}, {%8,%9}, {%0,%1,%2,%3};"
                        : "+f"(acc[mt][nt][0]), "+f"(acc[mt][nt][1]),
                          "+f"(acc[mt][nt][2]), "+f"(acc[mt][nt][3])
                        : "r"(a0), "r"(a1), "r"(a2), "r"(a3),
                          "r"(bf[nt][0]), "r"(bf[nt][1]));
                }
            }
        }
    }

    // epilogue
    float2 bb[4];
    if (bias) {
#pragma unroll
        for (int nt = 0; nt < 4; nt++) {
            int cc = col0 + nw + nt * 8 + 2 * tg;
            bb[nt].x = bias[cc];
            bb[nt].y = bias[cc + 1];
        }
    }
#pragma unroll
    for (int mt = 0; mt < 4; mt++) {
        int r = row0 + mw + mt * 16 + gid;
#pragma unroll
        for (int nt = 0; nt < 4; nt++) {
            int cc = col0 + nw + nt * 8 + 2 * tg;
            float2 v0 = make_float2(acc[mt][nt][0], acc[mt][nt][1]);
            float2 v1 = make_float2(acc[mt][nt][2], acc[mt][nt][3]);
            if (bias) {
                v0.x += bb[nt].x; v0.y += bb[nt].y;
                v1.x += bb[nt].x; v1.y += bb[nt].y;
            }
            if (relu) {
                v0.x = fmaxf(v0.x, 0.f); v0.y = fmaxf(v0.y, 0.f);
                v1.x = fmaxf(v1.x, 0.f); v1.y = fmaxf(v1.y, 0.f);
            }
            if (c_sel == 0) {
                if (r < NN)     *(float2*)&g_x[(size_t)r * DD + cc]       = v0;
                if (r + 8 < NN) *(float2*)&g_x[(size_t)(r + 8) * DD + cc] = v1;
            } else {
                if (r < NN)     *(__half2*)&g_hh[(size_t)r * DD + cc]       = __floats2half2_rn(v0.x, v0.y);
                if (r + 8 < NN) *(__half2*)&g_hh[(size_t)(r + 8) * DD + cc] = __floats2half2_rn(v1.x, v1.y);
            }
        }
    }
}

// ---------------------------------------------------------------------------
// Fused CSR aggregation (fp16 h): one warp per dst node, 4-edge unroll.
//   o[d] = relu( bias + dinv[d]^2 * h[d] + sum_{s in N(d)} dinv[s]dinv[d] h[s] )
// Lane holds 8 contiguous cols [lane*8, lane*8+8): ONE uint4 load per edge-row.
// ---------------------------------------------------------------------------
__device__ __forceinline__ void acc8(float* a, uint4 raw, float n) {
    const __half2* h2 = (const __half2*)&raw;
#pragma unroll
    for (int j = 0; j < 4; j++) {
        float2 f = __half22float2(h2[j]);
        a[2 * j + 0] += n * f.x;
        a[2 * j + 1] += n * f.y;
    }
}

__global__ void __launch_bounds__(256)
aggregate_kernel(const float* __restrict__ bias, float* __restrict__ Oin, int o_sel)
{
    float* o = (o_sel == 0) ? g_x : Oin;
    int warp = (blockIdx.x * blockDim.x + threadIdx.x) >> 5;
    int lane = threadIdx.x & 31;
    if (warp >= NN) return;
    const int d = warp;
    const float dv = g_dinv[d];

    float a[8];
    // self-loop init
    {
        uint4 raw = *((const uint4*)(g_hh + (size_t)d * DD) + lane);
        const __half2* h2 = (const __half2*)&raw;
        const float s2 = dv * dv;
#pragma unroll
        for (int j = 0; j < 4; j++) {
            float2 f = __half22float2(h2[j]);
            a[2 * j + 0] = s2 * f.x;
            a[2 * j + 1] = s2 * f.y;
        }
    }

    const int start = g_rowstart[d];
    const int end   = g_rowstart[d + 1];
    int i = start;
    for (; i + 4 <= end; i += 4) {
        int   s0 = g_esrc[i],     s1 = g_esrc[i + 1];
        int   s2 = g_esrc[i + 2], s3 = g_esrc[i + 3];
        float n0 = dv * g_dinv[s0], n1 = dv * g_dinv[s1];
        float n2 = dv * g_dinv[s2], n3 = dv * g_dinv[s3];
        uint4 r0 = *((const uint4*)(g_hh + (size_t)s0 * DD) + lane);
        uint4 r1 = *((const uint4*)(g_hh + (size_t)s1 * DD) + lane);
        uint4 r2 = *((const uint4*)(g_hh + (size_t)s2 * DD) + lane);
        uint4 r3 = *((const uint4*)(g_hh + (size_t)s3 * DD) + lane);
        acc8(a, r0, n0);
        acc8(a, r1, n1);
        acc8(a, r2, n2);
        acc8(a, r3, n3);
    }
    for (; i < end; i++) {
        int s0 = g_esrc[i];
        float n0 = dv * g_dinv[s0];
        uint4 r0 = *((const uint4*)(g_hh + (size_t)s0 * DD) + lane);
        acc8(a, r0, n0);
    }

    // bias + relu + store (cols lane*8 .. lane*8+7)
    const int cbase = lane * 8;
    float4 b0 = *(const float4*)&bias[cbase];
    float4 b1 = *(const float4*)&bias[cbase + 4];
    float4 v0, v1;
    v0.x = fmaxf(a[0] + b0.x, 0.f); v0.y = fmaxf(a[1] + b0.y, 0.f);
    v0.z = fmaxf(a[2] + b0.z, 0.f); v0.w = fmaxf(a[3] + b0.w, 0.f);
    v1.x = fmaxf(a[4] + b1.x, 0.f); v1.y = fmaxf(a[5] + b1.y, 0.f);
    v1.z = fmaxf(a[6] + b1.z, 0.f); v1.w = fmaxf(a[7] + b1.w, 0.f);
    float* orow = o + (size_t)d * DD + cbase;
    *(float4*)&orow[0] = v0;
    *(float4*)&orow[4] = v1;
}

// ---------------------------------------------------------------------------
// Launch — kernels only; no runtime API calls (graph-capture safe).
// ---------------------------------------------------------------------------
extern "C" void kernel_launch(void* const* d_in, const int* in_sizes, int n_in,
                              void* d_out, int out_size)
{
    const float* input  = (const float*)d_in[0];
    const int*   ei32   = (const int*)d_in[1];     // int32 view; dtype sniffed on device
    const float* weight = (const float*)d_in[2];
    const float* bias   = (const float*)d_in[3];
    const float* conv_w = (const float*)d_in[4];
    const float* conv_b = (const float*)d_in[5];
    float*       out    = (float*)d_out;

    // CSR build (6 kernels)
    init_kernel<<<(NN + 255) / 256, 256>>>(ei32);
    decode_hist_kernel<<<(ESTRIDE + 255) / 256, 256>>>(ei32);
    partial_sum_kernel<<<SCAN_NB, SCAN_BLK>>>();
    scan_partials_kernel<<<1, 128>>>();
    write_rows_kernel<<<SCAN_NB, SCAN_BLK>>>();
    fill_kernel<<<(ESTRIDE + 255) / 256, 256>>>();

    dim3 ggrid((NN + 127) / 128, DD / 128);

    // x = relu(input @ W + b)   (A = input, C = g_x fp32)
    gemm_kernel<<<ggrid, 256>>>(input, weight, bias, /*a_sel=*/0, /*c_sel=*/0, /*relu=*/1);

    const int agg_blocks = (NN * 32 + 255) / 256;   // warp per node
    for (int l = 0; l < 2; l++) {
        // h = x @ conv_w[l]   (A = g_x, C = g_hh fp16)
        gemm_kernel<<<ggrid, 256>>>(nullptr, conv_w + (size_t)l * DD * DD,
                                    nullptr, /*a_sel=*/1, /*c_sel=*/1, /*relu=*/0);
        // fused: self-loop + neighbor gather + bias + relu
        aggregate_kernel<<<agg_blocks, 256>>>(conv_b + l * DD,
                                              out, /*o_sel=*/(l == 0) ? 0 : 1);
    }
}

// round 15
// speedup vs baseline: 1.0063x; 1.0058x over previous
#include <cuda_runtime.h>
#include <cuda_fp16.h>
#include <cstdint>

#define NN 50000
#define NE 800000
#define DD 256
#define NTB 512
#define NBLK 98                  // single wave: 98 blocks <= 148 SMs
#define NTH (NTB * NBLK)         // 50176 threads
#define ASW 12    // As row stride in words (16 halves + pad) - conflict-free A frags
#define BSW 136   // Bs2 row stride in words (128 half2 + pad) - conflict-free B frags

// Static scratch (no allocations allowed): ~88 MB.
__device__ float g_x[NN * DD];                      // fp32 activations
__device__ __align__(16) __half g_hh[NN * DD];      // fp16 post-GEMM h
__device__ float g_dinv[NN];
__device__ int   g_src[NE];
__device__ int   g_dst[NE];
__device__ int   g_esrc[NE];        // CSR: src ids grouped by dst
__device__ int   g_cnt[NN];         // in-degree (edges only)
__device__ int   g_rowstart[NN + 1];
__device__ int   g_fill[NN];
__device__ int   g_bsum[NBLK];
__device__ int   g_odd_nonzero;     // dtype sniffer flag
__device__ unsigned g_bar;          // grid barrier counter (reset at kernel end)

// bitcast __half2 -> uint32_t
__device__ __forceinline__ uint32_t h2u(__half2 h) {
    union { __half2 h; uint32_t u; } c;
    c.h = h;
    return c.u;
}

// Software grid barrier (single-wave kernel only).
__device__ __forceinline__ void grid_bar(unsigned target) {
    __syncthreads();
    if (threadIdx.x == 0) {
        __threadfence();
        atomicAdd(&g_bar, 1u);
        while (atomicAdd(&g_bar, 0u) < target) {}
        __threadfence();
    }
    __syncthreads();
}

// ---------------------------------------------------------------------------
// ONE-kernel CSR build: zero+sniff -> decode+hist -> scan -> rows -> fill.
// 98 blocks x 512 threads, all resident; phases separated by grid_bar.
// Cross-block reads use __ldcg (L1 non-coherent within a launch).
// ---------------------------------------------------------------------------
__global__ void __launch_bounds__(NTB) csr_build_kernel(const int* __restrict__ ei32) {
    __shared__ int s[NTB];
    __shared__ int sb[128];
    const int t = threadIdx.x;
    const int b = blockIdx.x;
    const int i = b * NTB + t;           // node index / global thread id
    const int g = i;

    // -- phase 0: zero cnt; block 0 sniffs dtype (int64 => odd int32 words all 0)
    if (i < NN) g_cnt[i] = 0;
    if (b == 0) {
        int v = 0;
#pragma unroll
        for (int j = 0; j < 8; j++)      // 512 threads * 8 odd words = words [0,8192)
            v |= ei32[(t * 8 + j) * 2 + 1];
        s[t] = v;
        __syncthreads();
        for (int off = NTB / 2; off > 0; off >>= 1) {
            if (t < off) s[t] |= s[t + off];
            __syncthreads();
        }
        if (t == 0) g_odd_nonzero = (s[0] != 0);
    }
    grid_bar(1 * NBLK);

    // -- phase 1: decode + histogram (grid-stride, 4-batched for atomic MLP)
    const int i32 = __ldcg(&g_odd_nonzero);
    {
        int e = g;
        for (; e + 3 * NTH < NE; e += 4 * NTH) {
            int sv[4], dv[4];
#pragma unroll
            for (int j = 0; j < 4; j++) {
                int ee = e + j * NTH;
                if (i32) { sv[j] = ei32[ee]; dv[j] = ei32[NE + ee]; }
                else     { sv[j] = ei32[2 * ee]; dv[j] = ei32[2 * (NE + ee)]; }
            }
#pragma unroll
            for (int j = 0; j < 4; j++) {
                int ee = e + j * NTH;
                g_src[ee] = sv[j];
                g_dst[ee] = dv[j];
            }
#pragma unroll
            for (int j = 0; j < 4; j++) atomicAdd(&g_cnt[dv[j]], 1);
        }
        for (; e < NE; e += NTH) {
            int sv, dv;
            if (i32) { sv = ei32[e]; dv = ei32[NE + e]; }
            else     { sv = ei32[2 * e]; dv = ei32[2 * (NE + e)]; }
            g_src[e] = sv;
            g_dst[e] = dv;
            atomicAdd(&g_cnt[dv], 1);
        }
    }
    grid_bar(2 * NBLK);

    // -- phase 2: local inclusive scan of this block's 512 counts
    const int v = (i < NN) ? __ldcg(&g_cnt[i]) : 0;
    s[t] = v;
    __syncthreads();
    for (int off = 1; off < NTB; off <<= 1) {
        int x = s[t];
        int add = (t >= off) ? s[t - off] : 0;
        __syncthreads();
        s[t] = x + add;
        __syncthreads();
    }
    const int incl = s[t];
    if (t == NTB - 1) g_bsum[b] = s[NTB - 1];
    grid_bar(3 * NBLK);

    // -- phase 3: every block scans the 98 block sums itself (tiny), writes rows
    {
        int bv = (t < NBLK) ? __ldcg(&g_bsum[t]) : 0;
        if (t < 128) sb[t] = bv;
        __syncthreads();
        for (int off = 1; off < 128; off <<= 1) {
            int x = (t < 128) ? sb[t] : 0;
            int add = (t >= off && t < 128) ? sb[t - off] : 0;
            __syncthreads();
            if (t < 128) sb[t] = x + add;
            __syncthreads();
        }
        const int boff = (b > 0) ? sb[b - 1] : 0;   // exclusive block offset
        if (i < NN) {
            g_rowstart[i] = boff + incl - v;
            g_fill[i] = 0;
            g_dinv[i] = rsqrtf((float)v + 1.0f);    // +1 self loop
        }
        if (i == 0) g_rowstart[NN] = NE;
    }
    grid_bar(4 * NBLK);

    // -- phase 4: CSR fill (grid-stride, 4-batched cursors)
    {
        int e = g;
        for (; e + 3 * NTH < NE; e += 4 * NTH) {
            int sv[4], dv[4], pos[4];
#pragma unroll
            for (int j = 0; j < 4; j++) {      // own phase-1 writes: same thread
                sv[j] = g_src[e + j * NTH];
                dv[j] = g_dst[e + j * NTH];
            }
#pragma unroll
            for (int j = 0; j < 4; j++)
                pos[j] = __ldcg(&g_rowstart[dv[j]]) + atomicAdd(&g_fill[dv[j]], 1);
#pragma unroll
            for (int j = 0; j < 4; j++) g_esrc[pos[j]] = sv[j];
        }
        for (; e < NE; e += NTH) {
            int sv = g_src[e], dv = g_dst[e];
            int pos = __ldcg(&g_rowstart[dv]) + atomicAdd(&g_fill[dv], 1);
            g_esrc[pos] = sv;
        }
    }

    // -- reset barrier counter for graph replay (last arrival does it)
    __syncthreads();
    if (t == 0) {
        __threadfence();
        unsigned c = atomicAdd(&g_bar, 1u);
        if (c == 5u * NBLK - 1u) atomicExch(&g_bar, 0u);
    }
}

// ---------------------------------------------------------------------------
// FP16 tensor-core GEMM: C[M,256] = A[M,256] @ B[256,256] (+bias, +relu)
// 128x128 tile, 256 threads (8 warps, 2M x 4N), warp tile 64x32,
// mma.sync.m16n8k16.f16 (fp32 accum), BK=16, register-prefetch pipeline.
// a_sel: 0 -> A = Ain (external), 1 -> A = g_x
// c_sel: 0 -> C = g_x (fp32),     1 -> C = g_hh (fp16)
// ---------------------------------------------------------------------------
__global__ void __launch_bounds__(256)
gemm_kernel(const float* __restrict__ Ain, const float* __restrict__ B,
            const float* __restrict__ bias, int a_sel, int c_sel, int relu)
{
    const float* A = (a_sel == 0) ? Ain : g_x;

    __shared__ uint32_t As[128 * ASW];   // [m][k] halves (packed half2 words)
    __shared__ uint32_t Bs2[8 * BSW];    // [kpair][n] half2

    const int tid  = threadIdx.x;
    const int lane = tid & 31;
    const int w    = tid >> 5;
    const int mw   = (w & 1) << 6;
    const int nw   = (w >> 1) << 5;
    const int gid  = lane >> 2;
    const int tg   = lane & 3;
    const int row0 = blockIdx.x * 128;
    const int col0 = blockIdx.y * 128;

    const int ar0 = tid >> 2,          ak0 = (tid & 3) * 4;
    const int ar1 = (tid + 256) >> 2,  ak1 = ak0;
    const int bp  = tid >> 5;
    const int bn4 = (tid & 31) * 4;

    float acc[4][4][4];
#pragma unroll
    for (int mt = 0; mt < 4; mt++)
#pragma unroll
        for (int nt = 0; nt < 4; nt++)
#pragma unroll
            for (int q = 0; q < 4; q++) acc[mt][nt][q] = 0.0f;

    float4 av0, av1, bv0, bv1;

    // prefetch chunk 0
    {
        int r0 = row0 + ar0, r1 = row0 + ar1;
        av0 = (r0 < NN) ? *(const float4*)&A[(size_t)r0 * DD + ak0] : make_float4(0,0,0,0);
        av1 = (r1 < NN) ? *(const float4*)&A[(size_t)r1 * DD + ak1] : make_float4(0,0,0,0);
        bv0 = *(const float4*)&B[(size_t)(2 * bp)     * DD + col0 + bn4];
        bv1 = *(const float4*)&B[(size_t)(2 * bp + 1) * DD + col0 + bn4];
    }

    for (int c = 0; c < 16; c++) {
        __syncthreads();
        {
            uint2 aw;
            aw.x = h2u(__floats2half2_rn(av0.x, av0.y));
            aw.y = h2u(__floats2half2_rn(av0.z, av0.w));
            *(uint2*)&As[ar0 * ASW + (ak0 >> 1)] = aw;
            aw.x = h2u(__floats2half2_rn(av1.x, av1.y));
            aw.y = h2u(__floats2half2_rn(av1.z, av1.w));
            *(uint2*)&As[ar1 * ASW + (ak1 >> 1)] = aw;
            uint4 bw;
            bw.x = h2u(__floats2half2_rn(bv0.x, bv1.x));
            bw.y = h2u(__floats2half2_rn(bv0.y, bv1.y));
            bw.z = h2u(__floats2half2_rn(bv0.z, bv1.z));
            bw.w = h2u(__floats2half2_rn(bv0.w, bv1.w));
            *(uint4*)&Bs2[bp * BSW + bn4] = bw;
        }
        __syncthreads();
        if (c < 15) {
            int k0 = (c + 1) * 16;
            int r0 = row0 + ar0, r1 = row0 + ar1;
            av0 = (r0 < NN) ? *(const float4*)&A[(size_t)r0 * DD + k0 + ak0] : make_float4(0,0,0,0);
            av1 = (r1 < NN) ? *(const float4*)&A[(size_t)r1 * DD + k0 + ak1] : make_float4(0,0,0,0);
            bv0 = *(const float4*)&B[(size_t)(k0 + 2 * bp)     * DD + col0 + bn4];
            bv1 = *(const float4*)&B[(size_t)(k0 + 2 * bp + 1) * DD + col0 + bn4];
        }
        {
            uint32_t bf[4][2];
#pragma unroll
            for (int nt = 0; nt < 4; nt++) {
                int n = nw + nt * 8 + gid;
                bf[nt][0] = Bs2[tg * BSW + n];
                bf[nt][1] = Bs2[(tg + 4) * BSW + n];
            }
#pragma unroll
            for (int mt = 0; mt < 4; mt++) {
                int m = mw + mt * 16 + gid;
                uint32_t a0 = As[m * ASW + tg];
                uint32_t a1 = As[(m + 8) * ASW + tg];
                uint32_t a2 = As[m * ASW + tg + 4];
                uint32_t a3 = As[(m + 8) * ASW + tg + 4];
#pragma unroll
                for (int nt = 0; nt < 4; nt++) {
                    asm("mma.sync.aligned.m16n8k16.row.col.f32.f16.f16.f32 "
                        "{%0,%1,%2,%3}, {%4,%5,%6,%7}, {%8,%9}, {%0,%1,%2,%3};"
                        : "+f"(acc[mt][nt][0]), "+f"(acc[mt][nt][1]),
                          "+f"(acc[mt][nt][2]), "+f"(acc[mt][nt][3])
                        : "r"(a0), "r"(a1), "r"(a2), "r"(a3),
                          "r"(bf[nt][0]), "r"(bf[nt][1]));
                }
            }
        }
    }

    float2 bb[4];
    if (bias) {
#pragma unroll
        for (int nt = 0; nt < 4; nt++) {
            int cc = col0 + nw + nt * 8 + 2 * tg;
            bb[nt].x = bias[cc];
            bb[nt].y = bias[cc + 1];
        }
    }
#pragma unroll
    for (int mt = 0; mt < 4; mt++) {
        int r = row0 + mw + mt * 16 + gid;
#pragma unroll
        for (int nt = 0; nt < 4; nt++) {
            int cc = col0 + nw + nt * 8 + 2 * tg;
            float2 v0 = make_float2(acc[mt][nt][0], acc[mt][nt][1]);
            float2 v1 = make_float2(acc[mt][nt][2], acc[mt][nt][3]);
            if (bias) {
                v0.x += bb[nt].x; v0.y += bb[nt].y;
                v1.x += bb[nt].x; v1.y += bb[nt].y;
            }
            if (relu) {
                v0.x = fmaxf(v0.x, 0.f); v0.y = fmaxf(v0.y, 0.f);
                v1.x = fmaxf(v1.x, 0.f); v1.y = fmaxf(v1.y, 0.f);
            }
            if (c_sel == 0) {
                if (r < NN)     *(float2*)&g_x[(size_t)r * DD + cc]       = v0;
                if (r + 8 < NN) *(float2*)&g_x[(size_t)(r + 8) * DD + cc] = v1;
            } else {
                if (r < NN)     *(__half2*)&g_hh[(size_t)r * DD + cc]       = __floats2half2_rn(v0.x, v0.y);
                if (r + 8 < NN) *(__half2*)&g_hh[(size_t)(r + 8) * DD + cc] = __floats2half2_rn(v1.x, v1.y);
            }
        }
    }
}

// ---------------------------------------------------------------------------
// Fused CSR aggregation (fp16 h): one warp per dst node, 4-edge unroll.
//   o[d] = relu( bias + dinv[d]^2 * h[d] + sum_{s in N(d)} dinv[s]dinv[d] h[s] )
// Lane holds 8 contiguous cols: ONE uint4 load per edge-row.
// ---------------------------------------------------------------------------
__device__ __forceinline__ void acc8(float* a, uint4 raw, float n) {
    const __half2* h2 = (const __half2*)&raw;
#pragma unroll
    for (int j = 0; j < 4; j++) {
        float2 f = __half22float2(h2[j]);
        a[2 * j + 0] += n * f.x;
        a[2 * j + 1] += n * f.y;
    }
}

__global__ void __launch_bounds__(256)
aggregate_kernel(const float* __restrict__ bias, float* __restrict__ Oin, int o_sel)
{
    float* o = (o_sel == 0) ? g_x : Oin;
    int warp = (blockIdx.x * blockDim.x + threadIdx.x) >> 5;
    int lane = threadIdx.x & 31;
    if (warp >= NN) return;
    const int d = warp;
    const float dv = g_dinv[d];

    float a[8];
    {
        uint4 raw = *((const uint4*)(g_hh + (size_t)d * DD) + lane);
        const __half2* h2 = (const __half2*)&raw;
        const float s2 = dv * dv;
#pragma unroll
        for (int j = 0; j < 4; j++) {
            float2 f = __half22float2(h2[j]);
            a[2 * j + 0] = s2 * f.x;
            a[2 * j + 1] = s2 * f.y;
        }
    }

    const int start = g_rowstart[d];
    const int end   = g_rowstart[d + 1];
    int i = start;
    for (; i + 4 <= end; i += 4) {
        int   s0 = g_esrc[i],     s1 = g_esrc[i + 1];
        int   s2 = g_esrc[i + 2], s3 = g_esrc[i + 3];
        float n0 = dv * g_dinv[s0], n1 = dv * g_dinv[s1];
        float n2 = dv * g_dinv[s2], n3 = dv * g_dinv[s3];
        uint4 r0 = *((const uint4*)(g_hh + (size_t)s0 * DD) + lane);
        uint4 r1 = *((const uint4*)(g_hh + (size_t)s1 * DD) + lane);
        uint4 r2 = *((const uint4*)(g_hh + (size_t)s2 * DD) + lane);
        uint4 r3 = *((const uint4*)(g_hh + (size_t)s3 * DD) + lane);
        acc8(a, r0, n0);
        acc8(a, r1, n1);
        acc8(a, r2, n2);
        acc8(a, r3, n3);
    }
    for (; i < end; i++) {
        int s0 = g_esrc[i];
        float n0 = dv * g_dinv[s0];
        uint4 r0 = *((const uint4*)(g_hh + (size_t)s0 * DD) + lane);
        acc8(a, r0, n0);
    }

    const int cbase = lane * 8;
    float4 b0 = *(const float4*)&bias[cbase];
    float4 b1 = *(const float4*)&bias[cbase + 4];
    float4 v0, v1;
    v0.x = fmaxf(a[0] + b0.x, 0.f); v0.y = fmaxf(a[1] + b0.y, 0.f);
    v0.z = fmaxf(a[2] + b0.z, 0.f); v0.w = fmaxf(a[3] + b0.w, 0.f);
    v1.x = fmaxf(a[4] + b1.x, 0.f); v1.y = fmaxf(a[5] + b1.y, 0.f);
    v1.z = fmaxf(a[6] + b1.z, 0.f); v1.w = fmaxf(a[7] + b1.w, 0.f);
    float* orow = o + (size_t)d * DD + cbase;
    *(float4*)&orow[0] = v0;
    *(float4*)&orow[4] = v1;
}

// ---------------------------------------------------------------------------
// Launch — 6 kernels total; no runtime API calls (graph-capture safe).
// ---------------------------------------------------------------------------
extern "C" void kernel_launch(void* const* d_in, const int* in_sizes, int n_in,
                              void* d_out, int out_size)
{
    const float* input  = (const float*)d_in[0];
    const int*   ei32   = (const int*)d_in[1];     // int32 view; dtype sniffed on device
    const float* weight = (const float*)d_in[2];
    const float* bias   = (const float*)d_in[3];
    const float* conv_w = (const float*)d_in[4];
    const float* conv_b = (const float*)d_in[5];
    float*       out    = (float*)d_out;

    // CSR build: ONE persistent single-wave kernel
    csr_build_kernel<<<NBLK, NTB>>>(ei32);

    dim3 ggrid((NN + 127) / 128, DD / 128);

    // x = relu(input @ W + b)   (A = input, C = g_x fp32)
    gemm_kernel<<<ggrid, 256>>>(input, weight, bias, /*a_sel=*/0, /*c_sel=*/0, /*relu=*/1);

    const int agg_blocks = (NN * 32 + 255) / 256;   // warp per node
    for (int l = 0; l < 2; l++) {
        // h = x @ conv_w[l]   (A = g_x, C = g_hh fp16)
        gemm_kernel<<<ggrid, 256>>>(nullptr, conv_w + (size_t)l * DD * DD,
                                    nullptr, /*a_sel=*/1, /*c_sel=*/1, /*relu=*/0);
        // fused: self-loop + neighbor gather + bias + relu
        aggregate_kernel<<<agg_blocks, 256>>>(conv_b + l * DD,
                                              out, /*o_sel=*/(l == 0) ? 0 : 1);
    }
}

// round 16
// speedup vs baseline: 1.0717x; 1.0650x over previous
#include <cuda_runtime.h>
#include <cuda_fp16.h>
#include <cstdint>

#define NN 50000
#define NE 800000
#define DD 256
#define SCAN_BLK 512
#define SCAN_NB  ((NN + SCAN_BLK - 1) / SCAN_BLK)   // 98
#define ASW 12    // As row stride in words (16 halves + pad) - conflict-free A frags
#define BSW 136   // Bs2 row stride in words (128 half2 + pad) - conflict-free B frags

// Static scratch (no allocations allowed): ~88 MB.
__device__ float g_x[NN * DD];                      // fp32 activations
__device__ __align__(16) __half g_hh[NN * DD];      // fp16 h' = dinv * (x@W)
__device__ float g_dinv[NN];
__device__ int   g_src[NE];
__device__ int   g_dst[NE];
__device__ int   g_esrc[NE];        // CSR: src ids grouped by dst
__device__ int   g_cnt[NN];         // in-degree (edges only)
__device__ int   g_rowstart[NN + 1];
__device__ int   g_fill[NN];
__device__ int   g_bsum[SCAN_NB];
__device__ int   g_boff[SCAN_NB];
__device__ int   g_odd_nonzero;     // dtype sniffer flag

// bitcast __half2 -> uint32_t (no intrinsic exists for this direction)
__device__ __forceinline__ uint32_t h2u(__half2 h) {
    union { __half2 h; uint32_t u; } c;
    c.h = h;
    return c.u;
}

// ---------------------------------------------------------------------------
// Setup: dtype sniff, decode+histogram, 3-pass scan, CSR fill  (r11 structure)
// ---------------------------------------------------------------------------
__global__ void init_kernel() {
    int i = blockIdx.x * blockDim.x + threadIdx.x;
    if (i < NN) g_cnt[i] = 0;
    if (i == 0) g_odd_nonzero = 0;
}

// Sample first 8192 int32 words; int64 data => all odd words are zero.
__global__ void detect_kernel(const int* __restrict__ ei32) {
    int i = blockIdx.x * blockDim.x + threadIdx.x;   // 0..8191
    if ((i & 1) && ei32[i] != 0) atomicOr(&g_odd_nonzero, 1);
}

__global__ void decode_hist_kernel(const int* __restrict__ ei32) {
    int e = blockIdx.x * blockDim.x + threadIdx.x;
    if (e >= NE) return;
    int s, d;
    if (g_odd_nonzero) {            // genuinely int32: [src[NE] | dst[NE]]
        s = ei32[e];
        d = ei32[NE + e];
    } else {                        // int64: low words at even offsets
        s = ei32[2 * e];
        d = ei32[2 * (NE + e)];
    }
    g_src[e] = s;
    g_dst[e] = d;
    atomicAdd(&g_cnt[d], 1);
}

// Pass 1: per-block sums of g_cnt
__global__ void __launch_bounds__(SCAN_BLK) partial_sum_kernel() {
    __shared__ int s[SCAN_BLK];
    int t = threadIdx.x;
    int i = blockIdx.x * SCAN_BLK + t;
    s[t] = (i < NN) ? g_cnt[i] : 0;
    __syncthreads();
    for (int off = SCAN_BLK / 2; off > 0; off >>= 1) {
        if (t < off) s[t] += s[t + off];
        __syncthreads();
    }
    if (t == 0) g_bsum[blockIdx.x] = s[0];
}

// Pass 2: exclusive scan of 98 block sums (1 small block)
__global__ void __launch_bounds__(128) scan_partials_kernel() {
    __shared__ int s[128];
    int t = threadIdx.x;
    int v = (t < SCAN_NB) ? g_bsum[t] : 0;
    s[t] = v;
    __syncthreads();
    for (int off = 1; off < 128; off <<= 1) {
        int x = s[t];
        int add = (t >= off) ? s[t - off] : 0;
        __syncthreads();
        s[t] = x + add;
        __syncthreads();
    }
    if (t < SCAN_NB) g_boff[t] = s[t] - v;   // exclusive
}

// Pass 3: per-block local scan + offset; writes rowstart, dinv, fill
__global__ void __launch_bounds__(SCAN_BLK) write_rows_kernel() {
    __shared__ int s[SCAN_BLK];
    int t = threadIdx.x;
    int i = blockIdx.x * SCAN_BLK + t;
    int v = (i < NN) ? g_cnt[i] : 0;
    s[t] = v;
    __syncthreads();
    for (int off = 1; off < SCAN_BLK; off <<= 1) {
        int x = s[t];
        int add = (t >= off) ? s[t - off] : 0;
        __syncthreads();
        s[t] = x + add;
        __syncthreads();
    }
    if (i < NN) {
        g_rowstart[i] = g_boff[blockIdx.x] + s[t] - v;
        g_fill[i] = 0;
        g_dinv[i] = rsqrtf((float)v + 1.0f);   // +1 self loop
    }
    if (i == 0) g_rowstart[NN] = NE;
}

__global__ void fill_kernel() {
    int e = blockIdx.x * blockDim.x + threadIdx.x;
    if (e >= NE) return;
    int d = g_dst[e];
    int pos = g_rowstart[d] + atomicAdd(&g_fill[d], 1);
    g_esrc[pos] = g_src[e];
}

// ---------------------------------------------------------------------------
// FP16 tensor-core GEMM: C[M,256] = A[M,256] @ B[256,256] (+bias, +relu)
// 128x128 tile, 256 threads (8 warps, 2M x 4N), warp tile 64x32,
// mma.sync.m16n8k16.f16 (fp32 accum), BK=16, register-prefetch pipeline.
// a_sel: 0 -> A = Ain (external), 1 -> A = g_x
// c_sel: 0 -> C = g_x (fp32), 1 -> C = g_hh (fp16, PRE-SCALED by dinv[row])
// ---------------------------------------------------------------------------
__global__ void __launch_bounds__(256)
gemm_kernel(const float* __restrict__ Ain, const float* __restrict__ B,
            const float* __restrict__ bias, int a_sel, int c_sel, int relu)
{
    const float* A = (a_sel == 0) ? Ain : g_x;

    __shared__ uint32_t As[128 * ASW];   // [m][k] halves (packed half2 words)
    __shared__ uint32_t Bs2[8 * BSW];    // [kpair][n] half2

    const int tid  = threadIdx.x;
    const int lane = tid & 31;
    const int w    = tid >> 5;
    const int mw   = (w & 1) << 6;      // warp M offset: 0 / 64
    const int nw   = (w >> 1) << 5;     // warp N offset: 0/32/64/96
    const int gid  = lane >> 2;         // 0..7
    const int tg   = lane & 3;          // 0..3
    const int row0 = blockIdx.x * 128;
    const int col0 = blockIdx.y * 128;

    const int ar0 = tid >> 2,          ak0 = (tid & 3) * 4;
    const int ar1 = (tid + 256) >> 2,  ak1 = ak0;
    const int bp  = tid >> 5;
    const int bn4 = (tid & 31) * 4;

    float acc[4][4][4];
#pragma unroll
    for (int mt = 0; mt < 4; mt++)
#pragma unroll
        for (int nt = 0; nt < 4; nt++)
#pragma unroll
            for (int q = 0; q < 4; q++) acc[mt][nt][q] = 0.0f;

    float4 av0, av1, bv0, bv1;

    // prefetch chunk 0
    {
        int r0 = row0 + ar0, r1 = row0 + ar1;
        av0 = (r0 < NN) ? *(const float4*)&A[(size_t)r0 * DD + ak0] : make_float4(0,0,0,0);
        av1 = (r1 < NN) ? *(const float4*)&A[(size_t)r1 * DD + ak1] : make_float4(0,0,0,0);
        bv0 = *(const float4*)&B[(size_t)(2 * bp)     * DD + col0 + bn4];
        bv1 = *(const float4*)&B[(size_t)(2 * bp + 1) * DD + col0 + bn4];
    }

    for (int c = 0; c < 16; c++) {
        __syncthreads();
        // store prefetched chunk to smem (cvt to fp16)
        {
            uint2 aw;
            aw.x = h2u(__floats2half2_rn(av0.x, av0.y));
            aw.y = h2u(__floats2half2_rn(av0.z, av0.w));
            *(uint2*)&As[ar0 * ASW + (ak0 >> 1)] = aw;
            aw.x = h2u(__floats2half2_rn(av1.x, av1.y));
            aw.y = h2u(__floats2half2_rn(av1.z, av1.w));
            *(uint2*)&As[ar1 * ASW + (ak1 >> 1)] = aw;
            uint4 bw;
            bw.x = h2u(__floats2half2_rn(bv0.x, bv1.x));
            bw.y = h2u(__floats2half2_rn(bv0.y, bv1.y));
            bw.z = h2u(__floats2half2_rn(bv0.z, bv1.z));
            bw.w = h2u(__floats2half2_rn(bv0.w, bv1.w));
            *(uint4*)&Bs2[bp * BSW + bn4] = bw;
        }
        __syncthreads();
        // prefetch next chunk (latency hidden behind MMAs below)
        if (c < 15) {
            int k0 = (c + 1) * 16;
            int r0 = row0 + ar0, r1 = row0 + ar1;
            av0 = (r0 < NN) ? *(const float4*)&A[(size_t)r0 * DD + k0 + ak0] : make_float4(0,0,0,0);
            av1 = (r1 < NN) ? *(const float4*)&A[(size_t)r1 * DD + k0 + ak1] : make_float4(0,0,0,0);
            bv0 = *(const float4*)&B[(size_t)(k0 + 2 * bp)     * DD + col0 + bn4];
            bv1 = *(const float4*)&B[(size_t)(k0 + 2 * bp + 1) * DD + col0 + bn4];
        }
        // compute chunk c: one k16 step, 4x4 mma m16n8k16
        {
            uint32_t bf[4][2];
#pragma unroll
            for (int nt = 0; nt < 4; nt++) {
                int n = nw + nt * 8 + gid;
                bf[nt][0] = Bs2[tg * BSW + n];          // k = 2tg, 2tg+1
                bf[nt][1] = Bs2[(tg + 4) * BSW + n];    // k = 2tg+8, 2tg+9
            }
#pragma unroll
            for (int mt = 0; mt < 4; mt++) {
                int m = mw + mt * 16 + gid;
                uint32_t a0 = As[m * ASW + tg];
                uint32_t a1 = As[(m + 8) * ASW + tg];
                uint32_t a2 = As[m * ASW + tg + 4];
                uint32_t a3 = As[(m + 8) * ASW + tg + 4];
#pragma unroll
                for (int nt = 0; nt < 4; nt++) {
                    asm("mma.sync.aligned.m16n8k16.row.col.f32.f16.f16.f32 "
                        "{%0,%1,%2,%3}, {%4,%5,%6,%7}, {%8,%9}, {%0,%1,%2,%3};"
                        : "+f"(acc[mt][nt][0]), "+f"(acc[mt][nt][1]),
                          "+f"(acc[mt][nt][2]), "+f"(acc[mt][nt][3])
                        : "r"(a0), "r"(a1), "r"(a2), "r"(a3),
                          "r"(bf[nt][0]), "r"(bf[nt][1]));
                }
            }
        }
    }

    // epilogue: c0,c1 -> (row gid, cols 2tg,2tg+1); c2,c3 -> row gid+8
    float2 bb[4];
    if (bias) {
#pragma unroll
        for (int nt = 0; nt < 4; nt++) {
            int cc = col0 + nw + nt * 8 + 2 * tg;
            bb[nt].x = bias[cc];
            bb[nt].y = bias[cc + 1];
        }
    }
#pragma unroll
    for (int mt = 0; mt < 4; mt++) {
        int r = row0 + mw + mt * 16 + gid;
        // row scales for the fp16 h' output (pre-scale by dinv)
        float dv0 = 1.0f, dv1 = 1.0f;
        if (c_sel != 0) {
            if (r < NN)     dv0 = g_dinv[r];
            if (r + 8 < NN) dv1 = g_dinv[r + 8];
        }
#pragma unroll
        for (int nt = 0; nt < 4; nt++) {
            int cc = col0 + nw + nt * 8 + 2 * tg;
            float2 v0 = make_float2(acc[mt][nt][0], acc[mt][nt][1]);
            float2 v1 = make_float2(acc[mt][nt][2], acc[mt][nt][3]);
            if (bias) {
                v0.x += bb[nt].x; v0.y += bb[nt].y;
                v1.x += bb[nt].x; v1.y += bb[nt].y;
            }
            if (relu) {
                v0.x = fmaxf(v0.x, 0.f); v0.y = fmaxf(v0.y, 0.f);
                v1.x = fmaxf(v1.x, 0.f); v1.y = fmaxf(v1.y, 0.f);
            }
            if (c_sel == 0) {
                if (r < NN)     *(float2*)&g_x[(size_t)r * DD + cc]       = v0;
                if (r + 8 < NN) *(float2*)&g_x[(size_t)(r + 8) * DD + cc] = v1;
            } else {
                if (r < NN)
                    *(__half2*)&g_hh[(size_t)r * DD + cc] =
                        __floats2half2_rn(dv0 * v0.x, dv0 * v0.y);
                if (r + 8 < NN)
                    *(__half2*)&g_hh[(size_t)(r + 8) * DD + cc] =
                        __floats2half2_rn(dv1 * v1.x, dv1 * v1.y);
            }
        }
    }
}

// ---------------------------------------------------------------------------
// Fused CSR aggregation (pre-scaled fp16 h'): one warp per dst node.
//   o[d] = relu( bias + dinv[d] * ( h'[d] + sum_{s in N(d)} h'[s] ) )
// No per-edge norm: inner loop is index load + row LDG.128 + cvt + FADD only.
// ---------------------------------------------------------------------------
__device__ __forceinline__ void add8(float* a, uint4 raw) {
    const __half2* h2 = (const __half2*)&raw;
#pragma unroll
    for (int j = 0; j < 4; j++) {
        float2 f = __half22float2(h2[j]);
        a[2 * j + 0] += f.x;
        a[2 * j + 1] += f.y;
    }
}

__global__ void __launch_bounds__(256)
aggregate_kernel(const float* __restrict__ bias, float* __restrict__ Oin, int o_sel)
{
    float* o = (o_sel == 0) ? g_x : Oin;
    int warp = (blockIdx.x * blockDim.x + threadIdx.x) >> 5;
    int lane = threadIdx.x & 31;
    if (warp >= NN) return;
    const int d = warp;
    const float dv = g_dinv[d];

    float a[8];
    // self-loop init: raw h'[d]
    {
        uint4 raw = *((const uint4*)(g_hh + (size_t)d * DD) + lane);
        const __half2* h2 = (const __half2*)&raw;
#pragma unroll
        for (int j = 0; j < 4; j++) {
            float2 f = __half22float2(h2[j]);
            a[2 * j + 0] = f.x;
            a[2 * j + 1] = f.y;
        }
    }

    const int start = g_rowstart[d];
    const int end   = g_rowstart[d + 1];
    int i = start;
    for (; i + 4 <= end; i += 4) {
        int s0 = g_esrc[i],     s1 = g_esrc[i + 1];
        int s2 = g_esrc[i + 2], s3 = g_esrc[i + 3];
        uint4 r0 = *((const uint4*)(g_hh + (size_t)s0 * DD) + lane);
        uint4 r1 = *((const uint4*)(g_hh + (size_t)s1 * DD) + lane);
        uint4 r2 = *((const uint4*)(g_hh + (size_t)s2 * DD) + lane);
        uint4 r3 = *((const uint4*)(g_hh + (size_t)s3 * DD) + lane);
        add8(a, r0);
        add8(a, r1);
        add8(a, r2);
        add8(a, r3);
    }
    for (; i < end; i++) {
        int s0 = g_esrc[i];
        uint4 r0 = *((const uint4*)(g_hh + (size_t)s0 * DD) + lane);
        add8(a, r0);
    }

    // scale by dinv[d], bias + relu + store (cols lane*8 .. lane*8+7)
    const int cbase = lane * 8;
    float4 b0 = *(const float4*)&bias[cbase];
    float4 b1 = *(const float4*)&bias[cbase + 4];
    float4 v0, v1;
    v0.x = fmaxf(fmaf(dv, a[0], b0.x), 0.f);
    v0.y = fmaxf(fmaf(dv, a[1], b0.y), 0.f);
    v0.z = fmaxf(fmaf(dv, a[2], b0.z), 0.f);
    v0.w = fmaxf(fmaf(dv, a[3], b0.w), 0.f);
    v1.x = fmaxf(fmaf(dv, a[4], b1.x), 0.f);
    v1.y = fmaxf(fmaf(dv, a[5], b1.y), 0.f);
    v1.z = fmaxf(fmaf(dv, a[6], b1.z), 0.f);
    v1.w = fmaxf(fmaf(dv, a[7], b1.w), 0.f);
    float* orow = o + (size_t)d * DD + cbase;
    *(float4*)&orow[0] = v0;
    *(float4*)&orow[4] = v1;
}

// ---------------------------------------------------------------------------
// Launch — kernels only; no runtime API calls (graph-capture safe).
// ---------------------------------------------------------------------------
extern "C" void kernel_launch(void* const* d_in, const int* in_sizes, int n_in,
                              void* d_out, int out_size)
{
    const float* input  = (const float*)d_in[0];
    const int*   ei32   = (const int*)d_in[1];     // int32 view; dtype sniffed on device
    const float* weight = (const float*)d_in[2];
    const float* bias   = (const float*)d_in[3];
    const float* conv_w = (const float*)d_in[4];
    const float* conv_b = (const float*)d_in[5];
    float*       out    = (float*)d_out;

    // CSR build (r11-proven structure)
    init_kernel<<<(NN + 255) / 256, 256>>>();
    detect_kernel<<<8192 / 256, 256>>>(ei32);
    decode_hist_kernel<<<(NE + 255) / 256, 256>>>(ei32);
    partial_sum_kernel<<<SCAN_NB, SCAN_BLK>>>();
    scan_partials_kernel<<<1, 128>>>();
    write_rows_kernel<<<SCAN_NB, SCAN_BLK>>>();
    fill_kernel<<<(NE + 255) / 256, 256>>>();

    dim3 ggrid((NN + 127) / 128, DD / 128);

    // x = relu(input @ W + b)   (A = input, C = g_x fp32)
    gemm_kernel<<<ggrid, 256>>>(input, weight, bias, /*a_sel=*/0, /*c_sel=*/0, /*relu=*/1);

    const int agg_blocks = (NN * 32 + 255) / 256;   // warp per node
    for (int l = 0; l < 2; l++) {
        // h' = dinv * (x @ conv_w[l])   (A = g_x, C = g_hh fp16, pre-scaled)
        gemm_kernel<<<ggrid, 256>>>(nullptr, conv_w + (size_t)l * DD * DD,
                                    nullptr, /*a_sel=*/1, /*c_sel=*/1, /*relu=*/0);
        // fused: self-loop + neighbor sum + dinv scale + bias + relu
        aggregate_kernel<<<agg_blocks, 256>>>(conv_b + l * DD,
                                              out, /*o_sel=*/(l == 0) ? 0 : 1);
    }
}

// round 17
// speedup vs baseline: 1.1161x; 1.0415x over previous
#include <cuda_runtime.h>
#include <cuda_fp16.h>
#include <cstdint>

#define NN 50000
#define NE 800000
#define DD 256
#define SCAN_BLK 512
#define SCAN_NB  ((NN + SCAN_BLK - 1) / SCAN_BLK)   // 98
#define ASW 12    // As row stride in words (16 halves + pad) - conflict-free A frags
#define BSW 136   // Bs2 row stride in words (128 half2 + pad) - conflict-free B frags

// Static scratch (no allocations allowed): ~63 MB.
__device__ __align__(16) __half g_xh[NN * DD];      // fp16 activations
__device__ __align__(16) __half g_hh[NN * DD];      // fp16 h' = dinv * (x@W)
__device__ float g_dinv[NN];
__device__ int   g_src[NE];
__device__ int   g_dst[NE];
__device__ int   g_esrc[NE];        // CSR: src ids grouped by dst
__device__ int   g_cnt[NN];         // in-degree (edges only)
__device__ int   g_rowstart[NN + 1];
__device__ int   g_fill[NN];
__device__ int   g_bsum[SCAN_NB];
__device__ int   g_boff[SCAN_NB];
__device__ int   g_odd_nonzero;     // dtype sniffer flag

// bitcast __half2 -> uint32_t (no intrinsic exists for this direction)
__device__ __forceinline__ uint32_t h2u(__half2 h) {
    union { __half2 h; uint32_t u; } c;
    c.h = h;
    return c.u;
}

// ---------------------------------------------------------------------------
// Setup: dtype sniff, decode+histogram, 3-pass scan, CSR fill  (r11 structure)
// ---------------------------------------------------------------------------
__global__ void init_kernel() {
    int i = blockIdx.x * blockDim.x + threadIdx.x;
    if (i < NN) g_cnt[i] = 0;
    if (i == 0) g_odd_nonzero = 0;
}

// Sample first 8192 int32 words; int64 data => all odd words are zero.
__global__ void detect_kernel(const int* __restrict__ ei32) {
    int i = blockIdx.x * blockDim.x + threadIdx.x;   // 0..8191
    if ((i & 1) && ei32[i] != 0) atomicOr(&g_odd_nonzero, 1);
}

__global__ void decode_hist_kernel(const int* __restrict__ ei32) {
    int e = blockIdx.x * blockDim.x + threadIdx.x;
    if (e >= NE) return;
    int s, d;
    if (g_odd_nonzero) {            // genuinely int32: [src[NE] | dst[NE]]
        s = ei32[e];
        d = ei32[NE + e];
    } else {                        // int64: low words at even offsets
        s = ei32[2 * e];
        d = ei32[2 * (NE + e)];
    }
    g_src[e] = s;
    g_dst[e] = d;
    atomicAdd(&g_cnt[d], 1);
}

// Pass 1: per-block sums of g_cnt
__global__ void __launch_bounds__(SCAN_BLK) partial_sum_kernel() {
    __shared__ int s[SCAN_BLK];
    int t = threadIdx.x;
    int i = blockIdx.x * SCAN_BLK + t;
    s[t] = (i < NN) ? g_cnt[i] : 0;
    __syncthreads();
    for (int off = SCAN_BLK / 2; off > 0; off >>= 1) {
        if (t < off) s[t] += s[t + off];
        __syncthreads();
    }
    if (t == 0) g_bsum[blockIdx.x] = s[0];
}

// Pass 2: exclusive scan of 98 block sums (1 small block)
__global__ void __launch_bounds__(128) scan_partials_kernel() {
    __shared__ int s[128];
    int t = threadIdx.x;
    int v = (t < SCAN_NB) ? g_bsum[t] : 0;
    s[t] = v;
    __syncthreads();
    for (int off = 1; off < 128; off <<= 1) {
        int x = s[t];
        int add = (t >= off) ? s[t - off] : 0;
        __syncthreads();
        s[t] = x + add;
        __syncthreads();
    }
    if (t < SCAN_NB) g_boff[t] = s[t] - v;   // exclusive
}

// Pass 3: per-block local scan + offset; writes rowstart, dinv, fill
__global__ void __launch_bounds__(SCAN_BLK) write_rows_kernel() {
    __shared__ int s[SCAN_BLK];
    int t = threadIdx.x;
    int i = blockIdx.x * SCAN_BLK + t;
    int v = (i < NN) ? g_cnt[i] : 0;
    s[t] = v;
    __syncthreads();
    for (int off = 1; off < SCAN_BLK; off <<= 1) {
        int x = s[t];
        int add = (t >= off) ? s[t - off] : 0;
        __syncthreads();
        s[t] = x + add;
        __syncthreads();
    }
    if (i < NN) {
        g_rowstart[i] = g_boff[blockIdx.x] + s[t] - v;
        g_fill[i] = 0;
        g_dinv[i] = rsqrtf((float)v + 1.0f);   // +1 self loop
    }
    if (i == 0) g_rowstart[NN] = NE;
}

__global__ void fill_kernel() {
    int e = blockIdx.x * blockDim.x + threadIdx.x;
    if (e >= NE) return;
    int d = g_dst[e];
    int pos = g_rowstart[d] + atomicAdd(&g_fill[d], 1);
    g_esrc[pos] = g_src[e];
}

// ---------------------------------------------------------------------------
// FP16 tensor-core GEMM: C[M,256] = A[M,256] @ B[256,256] (+bias, +relu)
// 128x128 tile, 256 threads (8 warps, 2M x 4N), warp tile 64x32,
// mma.sync.m16n8k16.f16 (fp32 accum), BK=16, register-prefetch pipeline.
// a_sel: 0 -> A = Ain (fp32 external), 1 -> A = g_xh (fp16, no staging cvt)
// c_sel: 0 -> C = g_xh (fp16), 1 -> C = g_hh (fp16, PRE-SCALED by dinv[row])
// ---------------------------------------------------------------------------
__global__ void __launch_bounds__(256)
gemm_kernel(const float* __restrict__ Ain, const float* __restrict__ B,
            const float* __restrict__ bias, int a_sel, int c_sel, int relu)
{
    __shared__ uint32_t As[128 * ASW];   // [m][k] halves (packed half2 words)
    __shared__ uint32_t Bs2[8 * BSW];    // [kpair][n] half2

    const int tid  = threadIdx.x;
    const int lane = tid & 31;
    const int w    = tid >> 5;
    const int mw   = (w & 1) << 6;      // warp M offset: 0 / 64
    const int nw   = (w >> 1) << 5;     // warp N offset: 0/32/64/96
    const int gid  = lane >> 2;         // 0..7
    const int tg   = lane & 3;          // 0..3
    const int row0 = blockIdx.x * 128;
    const int col0 = blockIdx.y * 128;

    const int ar0 = tid >> 2,          ak0 = (tid & 3) * 4;
    const int ar1 = (tid + 256) >> 2,  ak1 = ak0;
    const int bp  = tid >> 5;
    const int bn4 = (tid & 31) * 4;

    float acc[4][4][4];
#pragma unroll
    for (int mt = 0; mt < 4; mt++)
#pragma unroll
        for (int nt = 0; nt < 4; nt++)
#pragma unroll
            for (int q = 0; q < 4; q++) acc[mt][nt][q] = 0.0f;

    float4 av0, av1;          // fp32 A path
    uint2  ah0, ah1;          // fp16 A path (4 halves each)
    float4 bv0, bv1;

    // prefetch chunk 0
    {
        int r0 = row0 + ar0, r1 = row0 + ar1;
        if (a_sel == 0) {
            av0 = (r0 < NN) ? *(const float4*)&Ain[(size_t)r0 * DD + ak0] : make_float4(0,0,0,0);
            av1 = (r1 < NN) ? *(const float4*)&Ain[(size_t)r1 * DD + ak1] : make_float4(0,0,0,0);
        } else {
            ah0 = (r0 < NN) ? *(const uint2*)&g_xh[(size_t)r0 * DD + ak0] : make_uint2(0, 0);
            ah1 = (r1 < NN) ? *(const uint2*)&g_xh[(size_t)r1 * DD + ak1] : make_uint2(0, 0);
        }
        bv0 = *(const float4*)&B[(size_t)(2 * bp)     * DD + col0 + bn4];
        bv1 = *(const float4*)&B[(size_t)(2 * bp + 1) * DD + col0 + bn4];
    }

    for (int c = 0; c < 16; c++) {
        __syncthreads();
        // store prefetched chunk to smem
        {
            uint2 w0, w1;
            if (a_sel == 0) {
                w0.x = h2u(__floats2half2_rn(av0.x, av0.y));
                w0.y = h2u(__floats2half2_rn(av0.z, av0.w));
                w1.x = h2u(__floats2half2_rn(av1.x, av1.y));
                w1.y = h2u(__floats2half2_rn(av1.z, av1.w));
            } else {
                w0 = ah0;
                w1 = ah1;
            }
            *(uint2*)&As[ar0 * ASW + (ak0 >> 1)] = w0;
            *(uint2*)&As[ar1 * ASW + (ak1 >> 1)] = w1;
            uint4 bw;
            bw.x = h2u(__floats2half2_rn(bv0.x, bv1.x));
            bw.y = h2u(__floats2half2_rn(bv0.y, bv1.y));
            bw.z = h2u(__floats2half2_rn(bv0.z, bv1.z));
            bw.w = h2u(__floats2half2_rn(bv0.w, bv1.w));
            *(uint4*)&Bs2[bp * BSW + bn4] = bw;
        }
        __syncthreads();
        // prefetch next chunk (latency hidden behind MMAs below)
        if (c < 15) {
            int k0 = (c + 1) * 16;
            int r0 = row0 + ar0, r1 = row0 + ar1;
            if (a_sel == 0) {
                av0 = (r0 < NN) ? *(const float4*)&Ain[(size_t)r0 * DD + k0 + ak0] : make_float4(0,0,0,0);
                av1 = (r1 < NN) ? *(const float4*)&Ain[(size_t)r1 * DD + k0 + ak1] : make_float4(0,0,0,0);
            } else {
                ah0 = (r0 < NN) ? *(const uint2*)&g_xh[(size_t)r0 * DD + k0 + ak0] : make_uint2(0, 0);
                ah1 = (r1 < NN) ? *(const uint2*)&g_xh[(size_t)r1 * DD + k0 + ak1] : make_uint2(0, 0);
            }
            bv0 = *(const float4*)&B[(size_t)(k0 + 2 * bp)     * DD + col0 + bn4];
            bv1 = *(const float4*)&B[(size_t)(k0 + 2 * bp + 1) * DD + col0 + bn4];
        }
        // compute chunk c: one k16 step, 4x4 mma m16n8k16
        {
            uint32_t bf[4][2];
#pragma unroll
            for (int nt = 0; nt < 4; nt++) {
                int n = nw + nt * 8 + gid;
                bf[nt][0] = Bs2[tg * BSW + n];          // k = 2tg, 2tg+1
                bf[nt][1] = Bs2[(tg + 4) * BSW + n];    // k = 2tg+8, 2tg+9
            }
#pragma unroll
            for (int mt = 0; mt < 4; mt++) {
                int m = mw + mt * 16 + gid;
                uint32_t a0 = As[m * ASW + tg];
                uint32_t a1 = As[(m + 8) * ASW + tg];
                uint32_t a2 = As[m * ASW + tg + 4];
                uint32_t a3 = As[(m + 8) * ASW + tg + 4];
#pragma unroll
                for (int nt = 0; nt < 4; nt++) {
                    asm("mma.sync.aligned.m16n8k16.row.col.f32.f16.f16.f32 "
                        "{%0,%1,%2,%3}, {%4,%5,%6,%7}, {%8,%9}, {%0,%1,%2,%3};"
                        : "+f"(acc[mt][nt][0]), "+f"(acc[mt][nt][1]),
                          "+f"(acc[mt][nt][2]), "+f"(acc[mt][nt][3])
                        : "r"(a0), "r"(a1), "r"(a2), "r"(a3),
                          "r"(bf[nt][0]), "r"(bf[nt][1]));
                }
            }
        }
    }

    // epilogue: c0,c1 -> (row gid, cols 2tg,2tg+1); c2,c3 -> row gid+8
    float2 bb[4];
    if (bias) {
#pragma unroll
        for (int nt = 0; nt < 4; nt++) {
            int cc = col0 + nw + nt * 8 + 2 * tg;
            bb[nt].x = bias[cc];
            bb[nt].y = bias[cc + 1];
        }
    }
#pragma unroll
    for (int mt = 0; mt < 4; mt++) {
        int r = row0 + mw + mt * 16 + gid;
        // row scales for the h' output (pre-scale by dinv)
        float dv0 = 1.0f, dv1 = 1.0f;
        if (c_sel != 0) {
            if (r < NN)     dv0 = g_dinv[r];
            if (r + 8 < NN) dv1 = g_dinv[r + 8];
        }
#pragma unroll
        for (int nt = 0; nt < 4; nt++) {
            int cc = col0 + nw + nt * 8 + 2 * tg;
            float2 v0 = make_float2(acc[mt][nt][0], acc[mt][nt][1]);
            float2 v1 = make_float2(acc[mt][nt][2], acc[mt][nt][3]);
            if (bias) {
                v0.x += bb[nt].x; v0.y += bb[nt].y;
                v1.x += bb[nt].x; v1.y += bb[nt].y;
            }
            if (relu) {
                v0.x = fmaxf(v0.x, 0.f); v0.y = fmaxf(v0.y, 0.f);
                v1.x = fmaxf(v1.x, 0.f); v1.y = fmaxf(v1.y, 0.f);
            }
            if (c_sel == 0) {
                if (r < NN)
                    *(__half2*)&g_xh[(size_t)r * DD + cc] = __floats2half2_rn(v0.x, v0.y);
                if (r + 8 < NN)
                    *(__half2*)&g_xh[(size_t)(r + 8) * DD + cc] = __floats2half2_rn(v1.x, v1.y);
            } else {
                if (r < NN)
                    *(__half2*)&g_hh[(size_t)r * DD + cc] =
                        __floats2half2_rn(dv0 * v0.x, dv0 * v0.y);
                if (r + 8 < NN)
                    *(__half2*)&g_hh[(size_t)(r + 8) * DD + cc] =
                        __floats2half2_rn(dv1 * v1.x, dv1 * v1.y);
            }
        }
    }
}

// ---------------------------------------------------------------------------
// Fused CSR aggregation (pre-scaled fp16 h'): one warp per dst node.
//   o[d] = relu( bias + dinv[d] * ( h'[d] + sum_{s in N(d)} h'[s] ) )
// o_sel: 0 -> g_xh (fp16 activations), 1 -> Oin (fp32 final output)
// ---------------------------------------------------------------------------
__device__ __forceinline__ void add8(float* a, uint4 raw) {
    const __half2* h2 = (const __half2*)&raw;
#pragma unroll
    for (int j = 0; j < 4; j++) {
        float2 f = __half22float2(h2[j]);
        a[2 * j + 0] += f.x;
        a[2 * j + 1] += f.y;
    }
}

__global__ void __launch_bounds__(256)
aggregate_kernel(const float* __restrict__ bias, float* __restrict__ Oin, int o_sel)
{
    int warp = (blockIdx.x * blockDim.x + threadIdx.x) >> 5;
    int lane = threadIdx.x & 31;
    if (warp >= NN) return;
    const int d = warp;
    const float dv = g_dinv[d];

    float a[8];
    // self-loop init: raw h'[d]
    {
        uint4 raw = *((const uint4*)(g_hh + (size_t)d * DD) + lane);
        const __half2* h2 = (const __half2*)&raw;
#pragma unroll
        for (int j = 0; j < 4; j++) {
            float2 f = __half22float2(h2[j]);
            a[2 * j + 0] = f.x;
            a[2 * j + 1] = f.y;
        }
    }

    const int start = g_rowstart[d];
    const int end   = g_rowstart[d + 1];
    int i = start;
    for (; i + 4 <= end; i += 4) {
        int s0 = g_esrc[i],     s1 = g_esrc[i + 1];
        int s2 = g_esrc[i + 2], s3 = g_esrc[i + 3];
        uint4 r0 = *((const uint4*)(g_hh + (size_t)s0 * DD) + lane);
        uint4 r1 = *((const uint4*)(g_hh + (size_t)s1 * DD) + lane);
        uint4 r2 = *((const uint4*)(g_hh + (size_t)s2 * DD) + lane);
        uint4 r3 = *((const uint4*)(g_hh + (size_t)s3 * DD) + lane);
        add8(a, r0);
        add8(a, r1);
        add8(a, r2);
        add8(a, r3);
    }
    for (; i < end; i++) {
        int s0 = g_esrc[i];
        uint4 r0 = *((const uint4*)(g_hh + (size_t)s0 * DD) + lane);
        add8(a, r0);
    }

    // scale by dinv[d], bias + relu + store (cols lane*8 .. lane*8+7)
    const int cbase = lane * 8;
    float4 b0 = *(const float4*)&bias[cbase];
    float4 b1 = *(const float4*)&bias[cbase + 4];
    float r0 = fmaxf(fmaf(dv, a[0], b0.x), 0.f);
    float r1 = fmaxf(fmaf(dv, a[1], b0.y), 0.f);
    float r2 = fmaxf(fmaf(dv, a[2], b0.z), 0.f);
    float r3 = fmaxf(fmaf(dv, a[3], b0.w), 0.f);
    float r4 = fmaxf(fmaf(dv, a[4], b1.x), 0.f);
    float r5 = fmaxf(fmaf(dv, a[5], b1.y), 0.f);
    float r6 = fmaxf(fmaf(dv, a[6], b1.z), 0.f);
    float r7 = fmaxf(fmaf(dv, a[7], b1.w), 0.f);
    if (o_sel == 0) {
        uint4 pw;
        pw.x = h2u(__floats2half2_rn(r0, r1));
        pw.y = h2u(__floats2half2_rn(r2, r3));
        pw.z = h2u(__floats2half2_rn(r4, r5));
        pw.w = h2u(__floats2half2_rn(r6, r7));
        *((uint4*)(g_xh + (size_t)d * DD) + lane) = pw;
    } else {
        float* orow = Oin + (size_t)d * DD + cbase;
        *(float4*)&orow[0] = make_float4(r0, r1, r2, r3);
        *(float4*)&orow[4] = make_float4(r4, r5, r6, r7);
    }
}

// ---------------------------------------------------------------------------
// Launch — kernels only; no runtime API calls (graph-capture safe).
// ---------------------------------------------------------------------------
extern "C" void kernel_launch(void* const* d_in, const int* in_sizes, int n_in,
                              void* d_out, int out_size)
{
    const float* input  = (const float*)d_in[0];
    const int*   ei32   = (const int*)d_in[1];     // int32 view; dtype sniffed on device
    const float* weight = (const float*)d_in[2];
    const float* bias   = (const float*)d_in[3];
    const float* conv_w = (const float*)d_in[4];
    const float* conv_b = (const float*)d_in[5];
    float*       out    = (float*)d_out;

    // CSR build (r11-proven structure)
    init_kernel<<<(NN + 255) / 256, 256>>>();
    detect_kernel<<<8192 / 256, 256>>>(ei32);
    decode_hist_kernel<<<(NE + 255) / 256, 256>>>(ei32);
    partial_sum_kernel<<<SCAN_NB, SCAN_BLK>>>();
    scan_partials_kernel<<<1, 128>>>();
    write_rows_kernel<<<SCAN_NB, SCAN_BLK>>>();
    fill_kernel<<<(NE + 255) / 256, 256>>>();

    dim3 ggrid((NN + 127) / 128, DD / 128);

    // x = relu(input @ W + b)   (A = fp32 input, C = g_xh fp16)
    gemm_kernel<<<ggrid, 256>>>(input, weight, bias, /*a_sel=*/0, /*c_sel=*/0, /*relu=*/1);

    const int agg_blocks = (NN * 32 + 255) / 256;   // warp per node
    for (int l = 0; l < 2; l++) {
        // h' = dinv * (x @ conv_w[l])   (A = g_xh fp16, C = g_hh fp16, pre-scaled)
        gemm_kernel<<<ggrid, 256>>>(nullptr, conv_w + (size_t)l * DD * DD,
                                    nullptr, /*a_sel=*/1, /*c_sel=*/1, /*relu=*/0);
        // fused: self-loop + neighbor sum + dinv scale + bias + relu
        aggregate_kernel<<<agg_blocks, 256>>>(conv_b + l * DD,
                                              out, /*o_sel=*/(l == 0) ? 0 : 1);
    }
}